// round 1
// baseline (speedup 1.0000x reference)
#include <cuda_runtime.h>
#include <cstdint>
#include <math.h>

#define NV 4096
#define DV 128
#define HD 64
#define RV 3
#define WPR 128   // 32-bit words per adjacency row

// ---------------- scratch (static device allocations are allowed) -------------
__device__ uint32_t g_bits[RV * NV * WPR];        // 6.3 MB packed adjacency
__device__ float g_Wh[RV * NV * HD];              // 3 MB
__device__ float g_fi[RV * NV];
__device__ float g_fj[RV * NV];
__device__ float g_m[RV * NV];                    // row max (post-lrelu)
__device__ float g_Hbuf[2 * NV * HD];             // H1, H2
__device__ float g_num[RV * 4 * NV * HD];         // per (r, j-split) numerators
__device__ float g_den[RV * 4 * NV];              // per (r, j-split) denominators

__device__ __forceinline__ float lrelu(float x) { return x > 0.f ? x : 0.2f * x; }

union F4U { float4 f4; unsigned long long u[2]; };

__device__ __forceinline__ void fma2(unsigned long long& d, unsigned long long a,
                                     unsigned long long b) {
    asm("fma.rn.f32x2 %0, %1, %2, %0;" : "+l"(d) : "l"(a), "l"(b));
}

// ---------------- 1. pack adjacency to bits ----------------------------------
__global__ void pack_kernel(const int* __restrict__ A0, const int* __restrict__ A1,
                            const int* __restrict__ A2) {
    unsigned long long t = (unsigned long long)blockIdx.x * 256ull + threadIdx.x;
    int r = (int)(t >> 24);                       // N*N = 2^24
    unsigned e = (unsigned)(t & 0xFFFFFFull);
    const int* A = (r == 0) ? A0 : (r == 1) ? A1 : A2;
    int v = A[e];
    unsigned mask = __ballot_sync(0xFFFFFFFFu, v != 0);
    if ((threadIdx.x & 31) == 0) g_bits[t >> 5] = mask;
}

// ---------------- 2. Wh = H @ W[r]  (+ f_i / f_j epilogue) --------------------
template <int K>
__global__ void gemm_wh_kernel(const float* __restrict__ Hext, int useExt,
                               const float* __restrict__ Wmat,
                               const float* __restrict__ avec) {
    const float* H = useExt ? Hext : g_Hbuf;      // layer2 reads H1 from scratch
    int r = blockIdx.y;
    int rowbase = blockIdx.x * 64;
    __shared__ float Hs[64][64];                  // [k][i]
    __shared__ float Wss[64][64];                 // [k][c]
    int tid = threadIdx.x;
    int tx = tid & 15, ty = tid >> 4;
    int i0 = ty * 4, c0 = tx * 4;
    float acc[4][4] = {};
    const float* Wr = Wmat + (size_t)r * K * HD;

    for (int kt = 0; kt < K; kt += 64) {
        {
            int i = tid >> 2, kk0 = (tid & 3) << 4;
            const float* src = H + (size_t)(rowbase + i) * K + kt + kk0;
#pragma unroll
            for (int q = 0; q < 4; q++) {
                float4 v = *(const float4*)(src + 4 * q);
                Hs[kk0 + 4 * q + 0][i] = v.x;
                Hs[kk0 + 4 * q + 1][i] = v.y;
                Hs[kk0 + 4 * q + 2][i] = v.z;
                Hs[kk0 + 4 * q + 3][i] = v.w;
            }
            const float4* wsrc = (const float4*)(Wr + (size_t)kt * HD);
            float4* wdst = (float4*)&Wss[0][0];
#pragma unroll
            for (int q = 0; q < 4; q++) wdst[tid + 256 * q] = wsrc[tid + 256 * q];
        }
        __syncthreads();
#pragma unroll 8
        for (int kk = 0; kk < 64; kk++) {
            float4 a = *(const float4*)&Hs[kk][i0];
            float4 b = *(const float4*)&Wss[kk][c0];
            float av[4] = {a.x, a.y, a.z, a.w};
            float bv[4] = {b.x, b.y, b.z, b.w};
#pragma unroll
            for (int ii = 0; ii < 4; ii++)
#pragma unroll
                for (int jj = 0; jj < 4; jj++)
                    acc[ii][jj] = fmaf(av[ii], bv[jj], acc[ii][jj]);
        }
        __syncthreads();
    }

    // write Wh; stash tile in Hs for the f-reduction
#pragma unroll
    for (int ii = 0; ii < 4; ii++) {
        float4 v = make_float4(acc[ii][0], acc[ii][1], acc[ii][2], acc[ii][3]);
        *(float4*)&g_Wh[((size_t)r * NV + rowbase + i0 + ii) * HD + c0] = v;
        *(float4*)&Hs[i0 + ii][c0] = v;
    }
    __syncthreads();

    int warp = tid >> 5, lane = tid & 31;
    const float* ar = avec + r * 2 * HD;
#pragma unroll
    for (int s = 0; s < 8; s++) {
        int i = warp * 8 + s;
        float h1 = Hs[i][lane], h2 = Hs[i][lane + 32];
        float pl = h1 * ar[lane] + h2 * ar[lane + 32];
        float pr = h1 * ar[HD + lane] + h2 * ar[HD + lane + 32];
#pragma unroll
        for (int o = 16; o; o >>= 1) {
            pl += __shfl_down_sync(0xFFFFFFFFu, pl, o);
            pr += __shfl_down_sync(0xFFFFFFFFu, pr, o);
        }
        if (lane == 0) {
            g_fi[r * NV + rowbase + i] = pl;
            g_fj[r * NV + rowbase + i] = pr;
        }
    }
}

// ---------------- 3. masked row max: m = lrelu(f_i + max_masked f_j) ----------
__global__ void rowmax_kernel() {
    int r = blockIdx.y;
    int warp = threadIdx.x >> 5, lane = threadIdx.x & 31;
    int i = blockIdx.x * 8 + warp;
    const uint32_t* br = g_bits + ((size_t)r * NV + i) * WPR;
    const float* fj = g_fj + r * NV;
    float mx = -INFINITY;
#pragma unroll
    for (int t = 0; t < 4; t++) {
        uint32_t w = br[lane + 32 * t];
        int jb = (lane + 32 * t) << 5;
        while (w) {
            int b = __ffs(w) - 1;
            w &= w - 1;
            mx = fmaxf(mx, fj[jb + b]);
        }
    }
#pragma unroll
    for (int o = 16; o; o >>= 1) mx = fmaxf(mx, __shfl_xor_sync(0xFFFFFFFFu, mx, o));
    if (lane == 0) {
        float fi = g_fi[r * NV + i];
        g_m[r * NV + i] = (mx == -INFINITY) ? -INFINITY : lrelu(fi + mx);
    }
}

// ---------------- 4. fused masked-softmax x Wh (flash style) ------------------
// grid: (32 row-tiles of 128, 3 relations, 4 j-splits of 1024); 128 threads.
__global__ void __launch_bounds__(128) attn_kernel() {
    int itile = blockIdx.x, r = blockIdx.y, split = blockIdx.z;
    int rowbase = itile * 128;
    int jb = split * 1024;
    __shared__ float fjs[1024];
    __shared__ float ws2[32][256];   // [k][2*i]  (pre-duplicated for f32x2)
    __shared__ float whs[32][64];    // [k][c]
    int tid = threadIdx.x;

    {   // stage fj for this split
        const float4* src = (const float4*)(g_fj + r * NV + jb);
        float4* dst = (float4*)fjs;
#pragma unroll
        for (int q = 0; q < 2; q++) dst[tid + 128 * q] = src[tid + 128 * q];
    }

    int gi = rowbase + tid;                       // fill phase: thread == row
    float fi = g_fi[r * NV + gi];
    float mi = g_m[r * NV + gi];
    const uint32_t* bitrow = g_bits + ((size_t)r * NV + gi) * WPR + (jb >> 5);

    int tx = tid & 7, ty = tid >> 3;              // GEMM phase mapping
    int c0 = tx * 8, i2 = ty * 16;                // i2 = 2 * (ty*8)
    unsigned long long acc[8][4] = {};            // 8 rows x 4 col-pairs (f32x2)
    float denacc = 0.f;
    __syncthreads();

    for (int ch = 0; ch < 32; ch++) {
        uint32_t w = bitrow[ch];
        const float* fjc = fjs + ch * 32;
#pragma unroll 8
        for (int k = 0; k < 32; k++) {
            float s = fi + fjc[k];
            s = s > 0.f ? s : 0.2f * s;
            float wv = ((w >> k) & 1u) ? __expf(s - mi) : 0.f;
            *(float2*)&ws2[k][2 * tid] = make_float2(wv, wv);
            denacc += wv;
        }
        {
            const float4* src =
                (const float4*)(g_Wh + ((size_t)r * NV + jb + ch * 32) * HD);
            float4* dst = (float4*)&whs[0][0];
#pragma unroll
            for (int q = 0; q < 4; q++) dst[tid + 128 * q] = src[tid + 128 * q];
        }
        __syncthreads();
#pragma unroll 4
        for (int k = 0; k < 32; k++) {
            F4U a0, a1, a2, a3, b0, b1;
            a0.f4 = *(const float4*)&ws2[k][i2];
            a1.f4 = *(const float4*)&ws2[k][i2 + 4];
            a2.f4 = *(const float4*)&ws2[k][i2 + 8];
            a3.f4 = *(const float4*)&ws2[k][i2 + 12];
            b0.f4 = *(const float4*)&whs[k][c0];
            b1.f4 = *(const float4*)&whs[k][c0 + 4];
            unsigned long long ap[8] = {a0.u[0], a0.u[1], a1.u[0], a1.u[1],
                                        a2.u[0], a2.u[1], a3.u[0], a3.u[1]};
            unsigned long long bp[4] = {b0.u[0], b0.u[1], b1.u[0], b1.u[1]};
#pragma unroll
            for (int ii = 0; ii < 8; ii++)
#pragma unroll
                for (int p = 0; p < 4; p++) fma2(acc[ii][p], ap[ii], bp[p]);
        }
        __syncthreads();
    }

    int i0 = ty * 8;
#pragma unroll
    for (int ii = 0; ii < 8; ii++) {
        float* dst = g_num +
            ((((size_t)r * 4 + split) * NV) + rowbase + i0 + ii) * HD + c0;
        F4U v0, v1;
        v0.u[0] = acc[ii][0]; v0.u[1] = acc[ii][1];
        v1.u[0] = acc[ii][2]; v1.u[1] = acc[ii][3];
        *(float4*)dst = v0.f4;
        *(float4*)(dst + 4) = v1.f4;
    }
    g_den[((size_t)r * 4 + split) * NV + gi] = denacc;
}

// ---------------- 5. combine splits/relations, bias, relu ---------------------
__global__ void combine_kernel(const float* __restrict__ bvec, int layer) {
    int gid = blockIdx.x * 256 + threadIdx.x;
    int i = gid >> 6, c = gid & 63;
    float v = bvec[c];
#pragma unroll
    for (int r = 0; r < RV; r++) {
        float num = 0.f, den = 0.f;
#pragma unroll
        for (int s = 0; s < 4; s++) {
            num += g_num[((((size_t)r * 4 + s) * NV) + i) * HD + c];
            den += g_den[((size_t)r * 4 + s) * NV + i];
        }
        if (den != 0.f) v += num / den;   // den==0 <=> isolated row (nan_to_num)
    }
    g_Hbuf[(size_t)layer * NV * HD + (size_t)i * HD + c] = fmaxf(v, 0.f);
}

// ---------------- 6. score head ----------------------------------------------
__global__ void score_kernel(const float* __restrict__ Wsv,
                             const float* __restrict__ bs,
                             float* __restrict__ out) {
    int warp = threadIdx.x >> 5, lane = threadIdx.x & 31;
    int i = blockIdx.x * 8 + warp;
    const float* h = g_Hbuf + (size_t)NV * HD + (size_t)i * HD;
    float v = h[lane] * Wsv[lane] + h[lane + 32] * Wsv[lane + 32];
#pragma unroll
    for (int o = 16; o; o >>= 1) v += __shfl_down_sync(0xFFFFFFFFu, v, o);
    if (lane == 0) out[i] = 1.f / (1.f + __expf(-(v + bs[0])));
}

// ---------------- launch ------------------------------------------------------
extern "C" void kernel_launch(void* const* d_in, const int* in_sizes, int n_in,
                              void* d_out, int out_size) {
    const float* Z  = (const float*)d_in[0];
    const int*   A0 = (const int*)d_in[1];
    const int*   A1 = (const int*)d_in[2];
    const int*   A2 = (const int*)d_in[3];
    const float* W1 = (const float*)d_in[4];
    const float* a1 = (const float*)d_in[5];
    const float* b1 = (const float*)d_in[6];
    const float* W2 = (const float*)d_in[7];
    const float* a2 = (const float*)d_in[8];
    const float* b2 = (const float*)d_in[9];
    const float* Ws = (const float*)d_in[10];
    const float* bs = (const float*)d_in[11];
    float* out = (float*)d_out;

    pack_kernel<<<196608, 256>>>(A0, A1, A2);

    // layer 1
    gemm_wh_kernel<128><<<dim3(64, 3), 256>>>(Z, 1, W1, a1);
    rowmax_kernel<<<dim3(512, 3), 256>>>();
    attn_kernel<<<dim3(32, 3, 4), 128>>>();
    combine_kernel<<<1024, 256>>>(b1, 0);

    // layer 2
    gemm_wh_kernel<64><<<dim3(64, 3), 256>>>(nullptr, 0, W2, a2);
    rowmax_kernel<<<dim3(512, 3), 256>>>();
    attn_kernel<<<dim3(32, 3, 4), 128>>>();
    combine_kernel<<<1024, 256>>>(b2, 1);

    score_kernel<<<512, 256>>>(Ws, bs, out);
}

// round 3
// speedup vs baseline: 2.7696x; 2.7696x over previous
#include <cuda_runtime.h>
#include <cuda_fp16.h>
#include <cstdint>
#include <math.h>

#define NV 4096
#define HD 64
#define RV 3
#define WPR 128   // 32-bit words per adjacency row

// ---------------- scratch ------------------------------------------------------
__device__ uint32_t g_bits[RV * NV * WPR];        // packed adjacency (6.3 MB)
__device__ float g_fi[RV * NV];
__device__ float g_fj[RV * NV];
__device__ float g_Mj[RV];
__device__ float g_Ei[RV * NV];                   // per-row factors
__device__ float g_Fi[RV * NV];
__device__ float g_Ti[RV * NV];
__device__ float g_Ej[RV * NV];                   // per-col factors
__device__ float g_Fj[RV * NV];
__device__ __half g_Whh[RV * NV * HD];            // Wh in f16, [r][j][c]
__device__ float g_Hbuf[2 * NV * HD];             // H1, H2
__device__ float g_num[RV * 4 * NV * HD];         // per (r, j-split) numerators
__device__ float g_den[RV * 4 * NV];

__device__ __forceinline__ float lrelu(float x) { return x > 0.f ? x : 0.2f * x; }

__device__ __forceinline__ void cpa16(uint32_t d, const void* s) {
    asm volatile("cp.async.cg.shared.global [%0], [%1], 16;" :: "r"(d), "l"(s));
}
__device__ __forceinline__ void cpa8(uint32_t d, const void* s) {
    asm volatile("cp.async.ca.shared.global [%0], [%1], 8;" :: "r"(d), "l"(s));
}
__device__ __forceinline__ void ldsm_x2t(uint32_t& b0, uint32_t& b1, uint32_t a) {
    asm volatile("ldmatrix.sync.aligned.m8n8.x2.trans.shared.b16 {%0,%1}, [%2];"
                 : "=r"(b0), "=r"(b1) : "r"(a));
}
__device__ __forceinline__ void mma16816(float* d, const uint32_t* a,
                                         uint32_t b0, uint32_t b1) {
    asm volatile(
        "mma.sync.aligned.m16n8k16.row.col.f32.f16.f16.f32 "
        "{%0,%1,%2,%3}, {%4,%5,%6,%7}, {%8,%9}, {%0,%1,%2,%3};"
        : "+f"(d[0]), "+f"(d[1]), "+f"(d[2]), "+f"(d[3])
        : "r"(a[0]), "r"(a[1]), "r"(a[2]), "r"(a[3]), "r"(b0), "r"(b1));
}

__device__ __forceinline__ float alphaf(float e, float f, float Ei, float Fi,
                                        float Ti, uint32_t on) {
    float v = (e > Ti) ? e * Ei : f * Fi;
    return on ? v : 0.f;
}

// ---------------- 1. pack adjacency to bits ------------------------------------
__global__ void pack_kernel(const int* __restrict__ A0, const int* __restrict__ A1,
                            const int* __restrict__ A2) {
    unsigned long long t = (unsigned long long)blockIdx.x * 256ull + threadIdx.x;
    int r = (int)(t >> 24);
    unsigned e = (unsigned)(t & 0xFFFFFFull);
    const int* A = (r == 0) ? A0 : (r == 1) ? A1 : A2;
    int v = A[e];
    unsigned mask = __ballot_sync(0xFFFFFFFFu, v != 0);
    if ((threadIdx.x & 31) == 0) g_bits[t >> 5] = mask;
}

// ---------------- 2. Wh = H @ W[r]; emits Whh(f16,[j][c]) + f_i/f_j -------------
template <int K>
__global__ void gemm_wh_kernel(const float* __restrict__ Hext, int useExt,
                               const float* __restrict__ Wmat,
                               const float* __restrict__ avec) {
    const float* H = useExt ? Hext : g_Hbuf;
    int r = blockIdx.y;
    int rowbase = blockIdx.x * 64;
    __shared__ float Hs[64][64];                  // [k][i] then reused [i][c]
    __shared__ float Wss[64][64];                 // [k][c]
    int tid = threadIdx.x;
    int tx = tid & 15, ty = tid >> 4;
    int i0 = ty * 4, c0 = tx * 4;
    float acc[4][4] = {};
    const float* Wr = Wmat + (size_t)r * K * HD;

    for (int kt = 0; kt < K; kt += 64) {
        {
            int i = tid >> 2, kk0 = (tid & 3) << 4;
            const float* src = H + (size_t)(rowbase + i) * K + kt + kk0;
#pragma unroll
            for (int q = 0; q < 4; q++) {
                float4 v = *(const float4*)(src + 4 * q);
                Hs[kk0 + 4 * q + 0][i] = v.x;
                Hs[kk0 + 4 * q + 1][i] = v.y;
                Hs[kk0 + 4 * q + 2][i] = v.z;
                Hs[kk0 + 4 * q + 3][i] = v.w;
            }
            const float4* wsrc = (const float4*)(Wr + (size_t)kt * HD);
            float4* wdst = (float4*)&Wss[0][0];
#pragma unroll
            for (int q = 0; q < 4; q++) wdst[tid + 256 * q] = wsrc[tid + 256 * q];
        }
        __syncthreads();
#pragma unroll 8
        for (int kk = 0; kk < 64; kk++) {
            float4 a = *(const float4*)&Hs[kk][i0];
            float4 b = *(const float4*)&Wss[kk][c0];
            float av[4] = {a.x, a.y, a.z, a.w};
            float bv[4] = {b.x, b.y, b.z, b.w};
#pragma unroll
            for (int ii = 0; ii < 4; ii++)
#pragma unroll
                for (int jj = 0; jj < 4; jj++)
                    acc[ii][jj] = fmaf(av[ii], bv[jj], acc[ii][jj]);
        }
        __syncthreads();
    }

    // stash output tile [i][c] in Hs
#pragma unroll
    for (int ii = 0; ii < 4; ii++)
        *(float4*)&Hs[i0 + ii][c0] =
            make_float4(acc[ii][0], acc[ii][1], acc[ii][2], acc[ii][3]);
    __syncthreads();

    // f16 Wh store: [j][c]
    {
        int i = tid >> 2, cb = (tid & 3) * 16;
        uint32_t h2v[8];
#pragma unroll
        for (int q = 0; q < 8; q++) {
            __half2 h = __floats2half2_rn(Hs[i][cb + 2 * q], Hs[i][cb + 2 * q + 1]);
            h2v[q] = *reinterpret_cast<uint32_t*>(&h);
        }
        uint32_t* dst =
            (uint32_t*)(g_Whh + ((size_t)(r * NV + rowbase + i)) * HD + cb);
        *(uint4*)dst = make_uint4(h2v[0], h2v[1], h2v[2], h2v[3]);
        *(uint4*)(dst + 4) = make_uint4(h2v[4], h2v[5], h2v[6], h2v[7]);
    }

    int warp = tid >> 5, lane = tid & 31;
    const float* ar = avec + r * 2 * HD;
#pragma unroll
    for (int s = 0; s < 8; s++) {
        int i = warp * 8 + s;
        float h1 = Hs[i][lane], h2 = Hs[i][lane + 32];
        float pl = h1 * ar[lane] + h2 * ar[lane + 32];
        float pr = h1 * ar[HD + lane] + h2 * ar[HD + lane + 32];
#pragma unroll
        for (int o = 16; o; o >>= 1) {
            pl += __shfl_down_sync(0xFFFFFFFFu, pl, o);
            pr += __shfl_down_sync(0xFFFFFFFFu, pr, o);
        }
        if (lane == 0) {
            g_fi[r * NV + rowbase + i] = pl;
            g_fj[r * NV + rowbase + i] = pr;
        }
    }
}

// ---------------- 3. global max of f_j per relation -----------------------------
__global__ void maxred_kernel() {
    int r = blockIdx.x, tid = threadIdx.x;
    __shared__ float s[256];
    float m = -INFINITY;
    for (int j = tid; j < NV; j += 256) m = fmaxf(m, g_fj[r * NV + j]);
    s[tid] = m;
    __syncthreads();
    for (int o = 128; o; o >>= 1) {
        if (tid < o) s[tid] = fmaxf(s[tid], s[tid + o]);
        __syncthreads();
    }
    if (tid == 0) g_Mj[r] = s[0];
}

// ---------------- 4. per-row / per-col softmax factors --------------------------
__global__ void prep_kernel() {
    int r = blockIdx.y;
    int i = blockIdx.x * 256 + threadIdx.x;
    float Mj = g_Mj[r];
    float fi = g_fi[r * NV + i], fj = g_fj[r * NV + i];
    float u = fi + Mj;
    float m = lrelu(u);
    g_Ei[r * NV + i] = __expf(u - m);
    g_Fi[r * NV + i] = __expf(0.2f * u - m);
    g_Ti[r * NV + i] = __expf(-u);
    g_Ej[r * NV + i] = __expf(fj - Mj);
    g_Fj[r * NV + i] = __expf(0.2f * (fj - Mj));
}

// ---------------- 5. fused alpha-gen + HMMA aggregation -------------------------
// grid (16 i-tiles of 256 rows, 3 r, 4 j-splits of 1024); 256 threads / 8 warps.
__global__ void __launch_bounds__(256, 2) attn_hmma_kernel() {
    int tid = threadIdx.x;
    int itile = blockIdx.x, r = blockIdx.y, split = blockIdx.z;
    int rowbase = itile * 256;
    int jw0 = split * 1024;

    __shared__ __align__(128) uint8_t sB[2][8192];   // 64j x 64c f16, SW128
    __shared__ uint32_t sBits[2][512];               // 256 rows x 2 words
    __shared__ float sEj[1024], sFj[1024];

    uint32_t sBu[2] = {(uint32_t)__cvta_generic_to_shared(&sB[0][0]),
                       (uint32_t)__cvta_generic_to_shared(&sB[1][0])};
    uint32_t sBitsu[2] = {(uint32_t)__cvta_generic_to_shared(&sBits[0][0]),
                          (uint32_t)__cvta_generic_to_shared(&sBits[1][0])};

    // stage Ej/Fj window (once)
    ((float4*)sEj)[tid] = ((const float4*)(g_Ej + r * NV + jw0))[tid];
    ((float4*)sFj)[tid] = ((const float4*)(g_Fj + r * NV + jw0))[tid];

    // chunk stager
    auto stage = [&](int ch, int buf) {
#pragma unroll
        for (int q = 0; q < 2; q++) {
            int g = tid + 256 * q;
            int j = g >> 3, c8 = g & 7;
            const __half* src =
                g_Whh + ((size_t)(r * NV + jw0 + ch * 64 + j)) * HD + c8 * 8;
            cpa16(sBu[buf] + j * 128 + 16 * (c8 ^ (j & 7)), src);
        }
        const uint32_t* bsrc = g_bits +
            ((size_t)(r * NV + rowbase + tid)) * WPR + split * 32 + ch * 2;
        cpa8(sBitsu[buf] + tid * 8, bsrc);
        asm volatile("cp.async.commit_group;" ::: "memory");
    };

    stage(0, 0);

    int l = tid & 31, w = tid >> 5;
    int g4 = l >> 2, tg = l & 3;
    int rowloc = w * 32 + g4;
    int rowg = rowbase + rowloc;
    float Ei4[4], Fi4[4], Ti4[4];
#pragma unroll
    for (int rr = 0; rr < 4; rr++) {
        Ei4[rr] = g_Ei[r * NV + rowg + rr * 8];
        Fi4[rr] = g_Fi[r * NV + rowg + rr * 8];
        Ti4[rr] = g_Ti[r * NV + rowg + rr * 8];
    }
    float acc[2][8][4] = {};
    float den4[4] = {};
    int lrow = l & 15, rlow = l & 7;

    for (int ch = 0; ch < 16; ch++) {
        int buf = ch & 1;
        asm volatile("cp.async.wait_group 0;" ::: "memory");
        __syncthreads();
        if (ch + 1 < 16) stage(ch + 1, buf ^ 1);
#pragma unroll
        for (int ks = 0; ks < 4; ks++) {
            int jc = ch * 64 + ks * 16 + tg * 2;
            float2 elo = *(const float2*)&sEj[jc];
            float2 ehi = *(const float2*)&sEj[jc + 8];
            float2 flo = *(const float2*)&sFj[jc];
            float2 fhi = *(const float2*)&sFj[jc + 8];
            uint32_t afr[2][4];
#pragma unroll
            for (int rr = 0; rr < 4; rr++) {
                uint32_t wb = sBits[buf][(rowloc + rr * 8) * 2 + (ks >> 1)];
                uint32_t t = wb >> (((ks & 1) << 4) + tg * 2);
                float v0 = alphaf(elo.x, flo.x, Ei4[rr], Fi4[rr], Ti4[rr], t & 1u);
                float v1 = alphaf(elo.y, flo.y, Ei4[rr], Fi4[rr], Ti4[rr], t & 2u);
                float v8 = alphaf(ehi.x, fhi.x, Ei4[rr], Fi4[rr], Ti4[rr], t & 256u);
                float v9 = alphaf(ehi.y, fhi.y, Ei4[rr], Fi4[rr], Ti4[rr], t & 512u);
                __half2 hlo = __floats2half2_rn(v0, v1);
                __half2 hhi = __floats2half2_rn(v8, v9);
                float2 dlo = __half22float2(hlo);
                float2 dhi = __half22float2(hhi);
                den4[rr] += (dlo.x + dlo.y) + (dhi.x + dhi.y);
                int mt = rr >> 1, hi = rr & 1;
                afr[mt][hi] = *reinterpret_cast<uint32_t*>(&hlo);
                afr[mt][2 + hi] = *reinterpret_cast<uint32_t*>(&hhi);
            }
            uint32_t rowaddr = sBu[buf] + (ks * 16 + lrow) * 128;
#pragma unroll
            for (int ng = 0; ng < 8; ng++) {
                uint32_t b0, b1;
                ldsm_x2t(b0, b1, rowaddr + 16 * (ng ^ rlow));
                mma16816(acc[0][ng], afr[0], b0, b1);
                mma16816(acc[1][ng], afr[1], b0, b1);
            }
        }
        __syncthreads();
    }

    // den: reduce across the 4 lanes of each quad, write
#pragma unroll
    for (int rr = 0; rr < 4; rr++) {
        den4[rr] += __shfl_xor_sync(0xFFFFFFFFu, den4[rr], 1);
        den4[rr] += __shfl_xor_sync(0xFFFFFFFFu, den4[rr], 2);
    }
    if (tg == 0) {
#pragma unroll
        for (int rr = 0; rr < 4; rr++)
            g_den[(size_t)(r * 4 + split) * NV + rowg + rr * 8] = den4[rr];
    }

    float* nb = g_num + (size_t)(r * 4 + split) * NV * HD;
#pragma unroll
    for (int mt = 0; mt < 2; mt++)
#pragma unroll
        for (int ng = 0; ng < 8; ng++) {
            int col = ng * 8 + tg * 2;
            int R0 = rowg + mt * 16;
            *(float2*)&nb[(size_t)R0 * HD + col] =
                make_float2(acc[mt][ng][0], acc[mt][ng][1]);
            *(float2*)&nb[(size_t)(R0 + 8) * HD + col] =
                make_float2(acc[mt][ng][2], acc[mt][ng][3]);
        }
}

// ---------------- 6. combine splits/relations, bias, relu -----------------------
__global__ void combine_kernel(const float* __restrict__ bvec, int layer) {
    int gid = blockIdx.x * 256 + threadIdx.x;
    int i = gid >> 6, c = gid & 63;
    float v = bvec[c];
#pragma unroll
    for (int r = 0; r < RV; r++) {
        float num = 0.f, den = 0.f;
#pragma unroll
        for (int s = 0; s < 4; s++) {
            num += g_num[(((size_t)(r * 4 + s) * NV) + i) * HD + c];
            den += g_den[(size_t)(r * 4 + s) * NV + i];
        }
        if (den != 0.f) v += num / den;
    }
    g_Hbuf[(size_t)layer * NV * HD + (size_t)i * HD + c] = fmaxf(v, 0.f);
}

// ---------------- 7. score head -------------------------------------------------
__global__ void score_kernel(const float* __restrict__ Wsv,
                             const float* __restrict__ bs,
                             float* __restrict__ out) {
    int warp = threadIdx.x >> 5, lane = threadIdx.x & 31;
    int i = blockIdx.x * 8 + warp;
    const float* h = g_Hbuf + (size_t)NV * HD + (size_t)i * HD;
    float v = h[lane] * Wsv[lane] + h[lane + 32] * Wsv[lane + 32];
#pragma unroll
    for (int o = 16; o; o >>= 1) v += __shfl_down_sync(0xFFFFFFFFu, v, o);
    if (lane == 0) out[i] = 1.f / (1.f + __expf(-(v + bs[0])));
}

// ---------------- launch --------------------------------------------------------
extern "C" void kernel_launch(void* const* d_in, const int* in_sizes, int n_in,
                              void* d_out, int out_size) {
    const float* Z  = (const float*)d_in[0];
    const int*   A0 = (const int*)d_in[1];
    const int*   A1 = (const int*)d_in[2];
    const int*   A2 = (const int*)d_in[3];
    const float* W1 = (const float*)d_in[4];
    const float* a1 = (const float*)d_in[5];
    const float* b1 = (const float*)d_in[6];
    const float* W2 = (const float*)d_in[7];
    const float* a2 = (const float*)d_in[8];
    const float* b2 = (const float*)d_in[9];
    const float* Ws = (const float*)d_in[10];
    const float* bs = (const float*)d_in[11];
    float* out = (float*)d_out;

    pack_kernel<<<196608, 256>>>(A0, A1, A2);

    // layer 1
    gemm_wh_kernel<128><<<dim3(64, 3), 256>>>(Z, 1, W1, a1);
    maxred_kernel<<<3, 256>>>();
    prep_kernel<<<dim3(16, 3), 256>>>();
    attn_hmma_kernel<<<dim3(16, 3, 4), 256>>>();
    combine_kernel<<<1024, 256>>>(b1, 0);

    // layer 2
    gemm_wh_kernel<64><<<dim3(64, 3), 256>>>(nullptr, 0, W2, a2);
    maxred_kernel<<<3, 256>>>();
    prep_kernel<<<dim3(16, 3), 256>>>();
    attn_hmma_kernel<<<dim3(16, 3, 4), 256>>>();
    combine_kernel<<<1024, 256>>>(b2, 1);

    score_kernel<<<512, 256>>>(Ws, bs, out);
}

// round 4
// speedup vs baseline: 4.1394x; 1.4946x over previous
#include <cuda_runtime.h>
#include <cuda_fp16.h>
#include <cstdint>
#include <math.h>

#define NV 4096
#define HD 64
#define RV 3
#define WPR 128   // 32-bit words per adjacency row

// ---------------- scratch ------------------------------------------------------
__device__ uint32_t g_bits[RV * NV * WPR];        // packed adjacency (6.3 MB)
__device__ float g_fi[RV * NV];
__device__ float g_fj[RV * NV];
__device__ float g_Ei[RV * NV];                   // per-row factors
__device__ float g_Fi[RV * NV];
__device__ float g_Ti[RV * NV];
__device__ float g_Ej[RV * NV];                   // per-col factors
__device__ float g_Fj[RV * NV];
__device__ __half g_Whh[RV * NV * HD];            // Wh in f16, [r][j][c]
__device__ float g_Hbuf[2 * NV * HD];             // H1, H2
__device__ float g_num[RV * 4 * NV * HD];         // per (r, j-split) numerators
__device__ float g_den[RV * 4 * NV];

__device__ __forceinline__ float lrelu(float x) { return x > 0.f ? x : 0.2f * x; }

__device__ __forceinline__ void cpa16(uint32_t d, const void* s) {
    asm volatile("cp.async.cg.shared.global [%0], [%1], 16;" :: "r"(d), "l"(s));
}
__device__ __forceinline__ void cpa8(uint32_t d, const void* s) {
    asm volatile("cp.async.ca.shared.global [%0], [%1], 8;" :: "r"(d), "l"(s));
}
__device__ __forceinline__ void ldsm_x2t(uint32_t& b0, uint32_t& b1, uint32_t a) {
    asm volatile("ldmatrix.sync.aligned.m8n8.x2.trans.shared.b16 {%0,%1}, [%2];"
                 : "=r"(b0), "=r"(b1) : "r"(a));
}
__device__ __forceinline__ void mma16816(float* d, const uint32_t* a,
                                         uint32_t b0, uint32_t b1) {
    asm volatile(
        "mma.sync.aligned.m16n8k16.row.col.f32.f16.f16.f32 "
        "{%0,%1,%2,%3}, {%4,%5,%6,%7}, {%8,%9}, {%0,%1,%2,%3};"
        : "+f"(d[0]), "+f"(d[1]), "+f"(d[2]), "+f"(d[3])
        : "r"(a[0]), "r"(a[1]), "r"(a[2]), "r"(a[3]), "r"(b0), "r"(b1));
}

__device__ __forceinline__ float alphaf(float e, float f, float Ei, float Fi,
                                        float Ti, uint32_t on) {
    float v = (e > Ti) ? e * Ei : f * Fi;
    return on ? v : 0.f;
}

// ---------------- 1. pack adjacency to bits (grid-stride, vectorized) ----------
__global__ void pack_kernel(const int* __restrict__ A0, const int* __restrict__ A1,
                            const int* __restrict__ A2) {
    const int TOTQ = RV * NV * NV / 4;            // int4 quads
    int stride = gridDim.x * blockDim.x;
    int lane = threadIdx.x & 31;
    for (int t = blockIdx.x * blockDim.x + threadIdx.x; t < TOTQ; t += stride) {
        int r = t >> 22;                          // (4t) >> 24
        const int4* A = (const int4*)((r == 0) ? A0 : (r == 1) ? A1 : A2);
        int4 v = A[t & 0x3FFFFF];
        uint32_t nib = (v.x != 0 ? 1u : 0u) | (v.y != 0 ? 2u : 0u) |
                       (v.z != 0 ? 4u : 0u) | (v.w != 0 ? 8u : 0u);
        uint32_t m = nib << ((lane & 7) * 4);
        m |= __shfl_xor_sync(0xFFFFFFFFu, m, 1);
        m |= __shfl_xor_sync(0xFFFFFFFFu, m, 2);
        m |= __shfl_xor_sync(0xFFFFFFFFu, m, 4);
        if ((lane & 7) == 0) g_bits[t >> 3] = m;
    }
}

// ---------------- 2. Wh = H @ W[r]; emits Whh(f16,[j][c]) + f_i/f_j -------------
template <int K>
__global__ void gemm_wh_kernel(const float* __restrict__ Hext, int useExt,
                               const float* __restrict__ Wmat,
                               const float* __restrict__ avec) {
    const float* H = useExt ? Hext : g_Hbuf;
    int r = blockIdx.y;
    int rowbase = blockIdx.x * 64;
    __shared__ float Hs[64][64];                  // [k][i] then reused [i][c]
    __shared__ float Wss[64][64];                 // [k][c]
    int tid = threadIdx.x;
    int tx = tid & 15, ty = tid >> 4;
    int i0 = ty * 4, c0 = tx * 4;
    float acc[4][4] = {};
    const float* Wr = Wmat + (size_t)r * K * HD;

    for (int kt = 0; kt < K; kt += 64) {
        {
            int i = tid >> 2, kk0 = (tid & 3) << 4;
            const float* src = H + (size_t)(rowbase + i) * K + kt + kk0;
#pragma unroll
            for (int q = 0; q < 4; q++) {
                float4 v = *(const float4*)(src + 4 * q);
                Hs[kk0 + 4 * q + 0][i] = v.x;
                Hs[kk0 + 4 * q + 1][i] = v.y;
                Hs[kk0 + 4 * q + 2][i] = v.z;
                Hs[kk0 + 4 * q + 3][i] = v.w;
            }
            const float4* wsrc = (const float4*)(Wr + (size_t)kt * HD);
            float4* wdst = (float4*)&Wss[0][0];
#pragma unroll
            for (int q = 0; q < 4; q++) wdst[tid + 256 * q] = wsrc[tid + 256 * q];
        }
        __syncthreads();
#pragma unroll 8
        for (int kk = 0; kk < 64; kk++) {
            float4 a = *(const float4*)&Hs[kk][i0];
            float4 b = *(const float4*)&Wss[kk][c0];
            float av[4] = {a.x, a.y, a.z, a.w};
            float bv[4] = {b.x, b.y, b.z, b.w};
#pragma unroll
            for (int ii = 0; ii < 4; ii++)
#pragma unroll
                for (int jj = 0; jj < 4; jj++)
                    acc[ii][jj] = fmaf(av[ii], bv[jj], acc[ii][jj]);
        }
        __syncthreads();
    }

#pragma unroll
    for (int ii = 0; ii < 4; ii++)
        *(float4*)&Hs[i0 + ii][c0] =
            make_float4(acc[ii][0], acc[ii][1], acc[ii][2], acc[ii][3]);
    __syncthreads();

    // f16 Wh store: [j][c]
    {
        int i = tid >> 2, cb = (tid & 3) * 16;
        uint32_t h2v[8];
#pragma unroll
        for (int q = 0; q < 8; q++) {
            __half2 h = __floats2half2_rn(Hs[i][cb + 2 * q], Hs[i][cb + 2 * q + 1]);
            h2v[q] = *reinterpret_cast<uint32_t*>(&h);
        }
        uint32_t* dst =
            (uint32_t*)(g_Whh + ((size_t)(r * NV + rowbase + i)) * HD + cb);
        *(uint4*)dst = make_uint4(h2v[0], h2v[1], h2v[2], h2v[3]);
        *(uint4*)(dst + 4) = make_uint4(h2v[4], h2v[5], h2v[6], h2v[7]);
    }

    int warp = tid >> 5, lane = tid & 31;
    const float* ar = avec + r * 2 * HD;
#pragma unroll
    for (int s = 0; s < 8; s++) {
        int i = warp * 8 + s;
        float h1 = Hs[i][lane], h2 = Hs[i][lane + 32];
        float pl = h1 * ar[lane] + h2 * ar[lane + 32];
        float pr = h1 * ar[HD + lane] + h2 * ar[HD + lane + 32];
#pragma unroll
        for (int o = 16; o; o >>= 1) {
            pl += __shfl_down_sync(0xFFFFFFFFu, pl, o);
            pr += __shfl_down_sync(0xFFFFFFFFu, pr, o);
        }
        if (lane == 0) {
            g_fi[r * NV + rowbase + i] = pl;
            g_fj[r * NV + rowbase + i] = pr;
        }
    }
}

// ---------------- 3. fused max(f_j) + softmax factors ---------------------------
// grid (16, 3): each block redundantly reduces the max, computes one slice.
__global__ void maxprep_kernel() {
    int r = blockIdx.y, tid = threadIdx.x;
    __shared__ float s[256];
    float m = -INFINITY;
    for (int j = tid; j < NV; j += 256) m = fmaxf(m, g_fj[r * NV + j]);
    s[tid] = m;
    __syncthreads();
    for (int o = 128; o; o >>= 1) {
        if (tid < o) s[tid] = fmaxf(s[tid], s[tid + o]);
        __syncthreads();
    }
    float Mj = s[0];
    int i = blockIdx.x * 256 + tid;
    float fi = g_fi[r * NV + i], fj = g_fj[r * NV + i];
    float u = fi + Mj;
    float mm = lrelu(u);
    g_Ei[r * NV + i] = __expf(u - mm);
    g_Fi[r * NV + i] = __expf(0.2f * u - mm);
    g_Ti[r * NV + i] = __expf(-u);
    g_Ej[r * NV + i] = __expf(fj - Mj);
    g_Fj[r * NV + i] = __expf(0.2f * (fj - Mj));
}

// ---------------- 4. fused alpha-gen + HMMA aggregation -------------------------
// grid (16 i-tiles of 256 rows, 3 r, 4 j-splits of 1024); 256 threads / 8 warps.
__global__ void __launch_bounds__(256, 2) attn_hmma_kernel() {
    int tid = threadIdx.x;
    int itile = blockIdx.x, r = blockIdx.y, split = blockIdx.z;
    int rowbase = itile * 256;
    int jw0 = split * 1024;

    __shared__ __align__(128) uint8_t sB[2][8192];   // 64j x 64c f16, SW128
    __shared__ uint32_t sBits[2][512];               // 256 rows x 2 words
    __shared__ float4 sEjP[256], sFjP[256];          // mma-k-permuted factors

    uint32_t sBu[2] = {(uint32_t)__cvta_generic_to_shared(&sB[0][0]),
                       (uint32_t)__cvta_generic_to_shared(&sB[1][0])};
    uint32_t sBitsu[2] = {(uint32_t)__cvta_generic_to_shared(&sBits[0][0]),
                          (uint32_t)__cvta_generic_to_shared(&sBits[1][0])};

    // stage Ej/Fj permuted: entry (jg, tg) = cols {16jg+2tg, +1, +8, +9}
    {
        int jg = tid >> 2, t2 = tid & 3;
        const float* Ejp = g_Ej + r * NV + jw0 + jg * 16 + t2 * 2;
        const float* Fjp = g_Fj + r * NV + jw0 + jg * 16 + t2 * 2;
        sEjP[tid] = make_float4(Ejp[0], Ejp[1], Ejp[8], Ejp[9]);
        sFjP[tid] = make_float4(Fjp[0], Fjp[1], Fjp[8], Fjp[9]);
    }

    auto stage = [&](int ch, int buf) {
#pragma unroll
        for (int q = 0; q < 2; q++) {
            int g = tid + 256 * q;
            int j = g >> 3, c8 = g & 7;
            const __half* src =
                g_Whh + ((size_t)(r * NV + jw0 + ch * 64 + j)) * HD + c8 * 8;
            cpa16(sBu[buf] + j * 128 + 16 * (c8 ^ (j & 7)), src);
        }
        const uint32_t* bsrc = g_bits +
            ((size_t)(r * NV + rowbase + tid)) * WPR + split * 32 + ch * 2;
        cpa8(sBitsu[buf] + tid * 8, bsrc);
        asm volatile("cp.async.commit_group;" ::: "memory");
    };

    stage(0, 0);

    int l = tid & 31, w = tid >> 5;
    int g4 = l >> 2, tg = l & 3;
    int rowloc = w * 32 + g4;
    int rowg = rowbase + rowloc;
    float Ei4[4], Fi4[4], Ti4[4];
#pragma unroll
    for (int rr = 0; rr < 4; rr++) {
        Ei4[rr] = g_Ei[r * NV + rowg + rr * 8];
        Fi4[rr] = g_Fi[r * NV + rowg + rr * 8];
        Ti4[rr] = g_Ti[r * NV + rowg + rr * 8];
    }
    float acc[2][8][4] = {};
    float accD[2][4] = {};                         // den via ones-column B
    uint32_t bone = (l < 4) ? 0x3C003C00u : 0u;    // B[k][0]=1 fragment
    int lrow = l & 15, rlow = l & 7;

    for (int ch = 0; ch < 16; ch++) {
        int buf = ch & 1;
        asm volatile("cp.async.wait_group 0;" ::: "memory");
        __syncthreads();
        if (ch + 1 < 16) stage(ch + 1, buf ^ 1);
        uint2 wb4[4];
#pragma unroll
        for (int rr = 0; rr < 4; rr++)
            wb4[rr] = *(const uint2*)&sBits[buf][(rowloc + rr * 8) * 2];
#pragma unroll
        for (int ks = 0; ks < 4; ks++) {
            float4 E = sEjP[(ch * 4 + ks) * 4 + tg];
            float4 F = sFjP[(ch * 4 + ks) * 4 + tg];
            uint32_t afr[2][4];
#pragma unroll
            for (int rr = 0; rr < 4; rr++) {
                uint32_t wb = (ks < 2) ? wb4[rr].x : wb4[rr].y;
                uint32_t t = wb >> (((ks & 1) << 4) + tg * 2);
                float v0 = alphaf(E.x, F.x, Ei4[rr], Fi4[rr], Ti4[rr], t & 1u);
                float v1 = alphaf(E.y, F.y, Ei4[rr], Fi4[rr], Ti4[rr], t & 2u);
                float v8 = alphaf(E.z, F.z, Ei4[rr], Fi4[rr], Ti4[rr], t & 256u);
                float v9 = alphaf(E.w, F.w, Ei4[rr], Fi4[rr], Ti4[rr], t & 512u);
                __half2 hlo = __floats2half2_rn(v0, v1);
                __half2 hhi = __floats2half2_rn(v8, v9);
                int mt = rr >> 1, hi = rr & 1;
                afr[mt][hi] = *reinterpret_cast<uint32_t*>(&hlo);
                afr[mt][2 + hi] = *reinterpret_cast<uint32_t*>(&hhi);
            }
            uint32_t rowaddr = sBu[buf] + (ks * 16 + lrow) * 128;
#pragma unroll
            for (int ng = 0; ng < 8; ng++) {
                uint32_t b0, b1;
                ldsm_x2t(b0, b1, rowaddr + 16 * (ng ^ rlow));
                mma16816(acc[0][ng], afr[0], b0, b1);
                mma16816(acc[1][ng], afr[1], b0, b1);
            }
            mma16816(accD[0], afr[0], bone, bone);
            mma16816(accD[1], afr[1], bone, bone);
        }
        __syncthreads();
    }

    if (tg == 0) {
#pragma unroll
        for (int mt = 0; mt < 2; mt++) {
            g_den[(size_t)(r * 4 + split) * NV + rowg + mt * 16] = accD[mt][0];
            g_den[(size_t)(r * 4 + split) * NV + rowg + mt * 16 + 8] = accD[mt][2];
        }
    }

    float* nb = g_num + (size_t)(r * 4 + split) * NV * HD;
#pragma unroll
    for (int mt = 0; mt < 2; mt++)
#pragma unroll
        for (int ng = 0; ng < 8; ng++) {
            int col = ng * 8 + tg * 2;
            int R0 = rowg + mt * 16;
            *(float2*)&nb[(size_t)R0 * HD + col] =
                make_float2(acc[mt][ng][0], acc[mt][ng][1]);
            *(float2*)&nb[(size_t)(R0 + 8) * HD + col] =
                make_float2(acc[mt][ng][2], acc[mt][ng][3]);
        }
}

// ---------------- 5. combine splits/relations, bias, relu -----------------------
__global__ void combine_kernel(const float* __restrict__ bvec, int layer) {
    int gid = blockIdx.x * 256 + threadIdx.x;
    int i = gid >> 6, c = gid & 63;
    float v = bvec[c];
#pragma unroll
    for (int r = 0; r < RV; r++) {
        float num = 0.f, den = 0.f;
#pragma unroll
        for (int s = 0; s < 4; s++) {
            num += g_num[(((size_t)(r * 4 + s) * NV) + i) * HD + c];
            den += g_den[(size_t)(r * 4 + s) * NV + i];
        }
        if (den != 0.f) v += num / den;
    }
    g_Hbuf[(size_t)layer * NV * HD + (size_t)i * HD + c] = fmaxf(v, 0.f);
}

// ---------------- 6. score head -------------------------------------------------
__global__ void score_kernel(const float* __restrict__ Wsv,
                             const float* __restrict__ bs,
                             float* __restrict__ out) {
    int warp = threadIdx.x >> 5, lane = threadIdx.x & 31;
    int i = blockIdx.x * 8 + warp;
    const float* h = g_Hbuf + (size_t)NV * HD + (size_t)i * HD;
    float v = h[lane] * Wsv[lane] + h[lane + 32] * Wsv[lane + 32];
#pragma unroll
    for (int o = 16; o; o >>= 1) v += __shfl_down_sync(0xFFFFFFFFu, v, o);
    if (lane == 0) out[i] = 1.f / (1.f + __expf(-(v + bs[0])));
}

// ---------------- launch --------------------------------------------------------
extern "C" void kernel_launch(void* const* d_in, const int* in_sizes, int n_in,
                              void* d_out, int out_size) {
    const float* Z  = (const float*)d_in[0];
    const int*   A0 = (const int*)d_in[1];
    const int*   A1 = (const int*)d_in[2];
    const int*   A2 = (const int*)d_in[3];
    const float* W1 = (const float*)d_in[4];
    const float* a1 = (const float*)d_in[5];
    const float* b1 = (const float*)d_in[6];
    const float* W2 = (const float*)d_in[7];
    const float* a2 = (const float*)d_in[8];
    const float* b2 = (const float*)d_in[9];
    const float* Ws = (const float*)d_in[10];
    const float* bs = (const float*)d_in[11];
    float* out = (float*)d_out;

    pack_kernel<<<4096, 256>>>(A0, A1, A2);

    // layer 1
    gemm_wh_kernel<128><<<dim3(64, 3), 256>>>(Z, 1, W1, a1);
    maxprep_kernel<<<dim3(16, 3), 256>>>();
    attn_hmma_kernel<<<dim3(16, 3, 4), 256>>>();
    combine_kernel<<<1024, 256>>>(b1, 0);

    // layer 2
    gemm_wh_kernel<64><<<dim3(64, 3), 256>>>(nullptr, 0, W2, a2);
    maxprep_kernel<<<dim3(16, 3), 256>>>();
    attn_hmma_kernel<<<dim3(16, 3, 4), 256>>>();
    combine_kernel<<<1024, 256>>>(b2, 1);

    score_kernel<<<512, 256>>>(Ws, bs, out);
}

// round 5
// speedup vs baseline: 5.2735x; 1.2740x over previous
#include <cuda_runtime.h>
#include <cuda_fp16.h>
#include <cstdint>
#include <math.h>

#define NV 4096
#define HD 64
#define RV 3
#define WPR 128   // 32-bit words per adjacency row

// ---------------- scratch ------------------------------------------------------
__device__ uint32_t g_bits[RV * NV * WPR];        // packed adjacency (6.3 MB)
__device__ float g_fi[RV * NV];
__device__ float g_fj[RV * NV];
__device__ uint32_t g_EFi[RV * NV];               // half2(Ei, Fi) per row
__device__ uint4 g_EFj[RV * 256 * 4];             // per 16-j group x tg: {E2lo,E2hi,F2lo,F2hi}
__device__ __half g_Whh[RV * NV * HD];            // Wh in f16, [r][j][c]
__device__ float g_Hbuf[NV * HD];                 // H1
__device__ float g_num[RV * 4 * NV * HD];         // per (r, j-split) numerators
__device__ float g_den[RV * 4 * NV];

__device__ __forceinline__ float lrelu(float x) { return x > 0.f ? x : 0.2f * x; }

__device__ __forceinline__ void cpa16(uint32_t d, const void* s) {
    asm volatile("cp.async.cg.shared.global [%0], [%1], 16;" :: "r"(d), "l"(s));
}
__device__ __forceinline__ void mma16816(float* d, const uint32_t* a,
                                         uint32_t b0, uint32_t b1) {
    asm volatile(
        "mma.sync.aligned.m16n8k16.row.col.f32.f16.f16.f32 "
        "{%0,%1,%2,%3}, {%4,%5,%6,%7}, {%8,%9}, {%0,%1,%2,%3};"
        : "+f"(d[0]), "+f"(d[1]), "+f"(d[2]), "+f"(d[3])
        : "r"(a[0]), "r"(a[1]), "r"(a[2]), "r"(a[3]), "r"(b0), "r"(b1));
}

// ---------------- 1. pack adjacency to bits (grid-stride, vectorized) ----------
__global__ void pack_kernel(const int* __restrict__ A0, const int* __restrict__ A1,
                            const int* __restrict__ A2) {
    const int TOTQ = RV * NV * NV / 4;            // int4 quads
    int stride = gridDim.x * blockDim.x;
    int lane = threadIdx.x & 31;
    for (int t = blockIdx.x * blockDim.x + threadIdx.x; t < TOTQ; t += stride) {
        int r = t >> 22;                          // (4t) >> 24
        const int4* A = (const int4*)((r == 0) ? A0 : (r == 1) ? A1 : A2);
        int4 v = A[t & 0x3FFFFF];
        uint32_t nib = (v.x != 0 ? 1u : 0u) | (v.y != 0 ? 2u : 0u) |
                       (v.z != 0 ? 4u : 0u) | (v.w != 0 ? 8u : 0u);
        uint32_t m = nib << ((lane & 7) * 4);
        m |= __shfl_xor_sync(0xFFFFFFFFu, m, 1);
        m |= __shfl_xor_sync(0xFFFFFFFFu, m, 2);
        m |= __shfl_xor_sync(0xFFFFFFFFu, m, 4);
        if ((lane & 7) == 0) g_bits[t >> 3] = m;
    }
}

// ---------------- 2. Wh = H @ W[r]; emits Whh(f16,[j][c]) + f_i/f_j -------------
template <int K>
__global__ void gemm_wh_kernel(const float* __restrict__ Hext, int useExt,
                               const float* __restrict__ Wmat,
                               const float* __restrict__ avec) {
    const float* H = useExt ? Hext : g_Hbuf;
    int r = blockIdx.y;
    int rowbase = blockIdx.x * 64;
    __shared__ float Hs[64][64];                  // [k][i] then reused [i][c]
    __shared__ float Wss[64][64];                 // [k][c]
    int tid = threadIdx.x;
    int tx = tid & 15, ty = tid >> 4;
    int i0 = ty * 4, c0 = tx * 4;
    float acc[4][4] = {};
    const float* Wr = Wmat + (size_t)r * K * HD;

    for (int kt = 0; kt < K; kt += 64) {
        {
            int i = tid >> 2, kk0 = (tid & 3) << 4;
            const float* src = H + (size_t)(rowbase + i) * K + kt + kk0;
#pragma unroll
            for (int q = 0; q < 4; q++) {
                float4 v = *(const float4*)(src + 4 * q);
                Hs[kk0 + 4 * q + 0][i] = v.x;
                Hs[kk0 + 4 * q + 1][i] = v.y;
                Hs[kk0 + 4 * q + 2][i] = v.z;
                Hs[kk0 + 4 * q + 3][i] = v.w;
            }
            const float4* wsrc = (const float4*)(Wr + (size_t)kt * HD);
            float4* wdst = (float4*)&Wss[0][0];
#pragma unroll
            for (int q = 0; q < 4; q++) wdst[tid + 256 * q] = wsrc[tid + 256 * q];
        }
        __syncthreads();
#pragma unroll 8
        for (int kk = 0; kk < 64; kk++) {
            float4 a = *(const float4*)&Hs[kk][i0];
            float4 b = *(const float4*)&Wss[kk][c0];
            float av[4] = {a.x, a.y, a.z, a.w};
            float bv[4] = {b.x, b.y, b.z, b.w};
#pragma unroll
            for (int ii = 0; ii < 4; ii++)
#pragma unroll
                for (int jj = 0; jj < 4; jj++)
                    acc[ii][jj] = fmaf(av[ii], bv[jj], acc[ii][jj]);
        }
        __syncthreads();
    }

#pragma unroll
    for (int ii = 0; ii < 4; ii++)
        *(float4*)&Hs[i0 + ii][c0] =
            make_float4(acc[ii][0], acc[ii][1], acc[ii][2], acc[ii][3]);
    __syncthreads();

    // f16 Wh store: [j][c]
    {
        int i = tid >> 2, cb = (tid & 3) * 16;
        uint32_t h2v[8];
#pragma unroll
        for (int q = 0; q < 8; q++) {
            __half2 h = __floats2half2_rn(Hs[i][cb + 2 * q], Hs[i][cb + 2 * q + 1]);
            h2v[q] = *reinterpret_cast<uint32_t*>(&h);
        }
        uint32_t* dst =
            (uint32_t*)(g_Whh + ((size_t)(r * NV + rowbase + i)) * HD + cb);
        *(uint4*)dst = make_uint4(h2v[0], h2v[1], h2v[2], h2v[3]);
        *(uint4*)(dst + 4) = make_uint4(h2v[4], h2v[5], h2v[6], h2v[7]);
    }

    int warp = tid >> 5, lane = tid & 31;
    const float* ar = avec + r * 2 * HD;
#pragma unroll
    for (int s = 0; s < 8; s++) {
        int i = warp * 8 + s;
        float h1 = Hs[i][lane], h2 = Hs[i][lane + 32];
        float pl = h1 * ar[lane] + h2 * ar[lane + 32];
        float pr = h1 * ar[HD + lane] + h2 * ar[HD + lane + 32];
#pragma unroll
        for (int o = 16; o; o >>= 1) {
            pl += __shfl_down_sync(0xFFFFFFFFu, pl, o);
            pr += __shfl_down_sync(0xFFFFFFFFu, pr, o);
        }
        if (lane == 0) {
            g_fi[r * NV + rowbase + i] = pl;
            g_fj[r * NV + rowbase + i] = pr;
        }
    }
}

// ---------------- 3. fused max(f_j) + softmax factors (f16 packed) --------------
__global__ void maxprep_kernel() {
    int r = blockIdx.y, tid = threadIdx.x;
    __shared__ float s[256];
    float m = -INFINITY;
    for (int j = tid; j < NV; j += 256) m = fmaxf(m, g_fj[r * NV + j]);
    s[tid] = m;
    __syncthreads();
    for (int o = 128; o; o >>= 1) {
        if (tid < o) s[tid] = fmaxf(s[tid], s[tid + o]);
        __syncthreads();
    }
    float Mj = s[0];
    int i = blockIdx.x * 256 + tid;
    float fi = g_fi[r * NV + i], fj = g_fj[r * NV + i];
    float u = fi + Mj;
    float mm = lrelu(u);
    __half2 efi = __floats2half2_rn(__expf(u - mm), __expf(0.2f * u - mm));
    g_EFi[r * NV + i] = *reinterpret_cast<uint32_t*>(&efi);
    // scatter Ej/Fj into the lane-permuted uint4 layout
    int g = i >> 4, j16 = i & 15, t = j16 >> 2, q = j16 & 3;
    __half* dst = (__half*)g_EFj + (size_t)r * NV * 2 + (g * 4 + t) * 8 + q;
    dst[0] = __float2half_rn(__expf(fj - Mj));
    dst[4] = __float2half_rn(__expf(0.2f * (fj - Mj)));
}

// ---------------- 4. fused alpha-gen + HMMA aggregation -------------------------
// grid (32 i-tiles of 128 rows, 3 r, 4 j-splits of 1024); 256 threads / 8 warps.
__global__ void __launch_bounds__(256, 3) attn_hmma_kernel() {
    int tid = threadIdx.x;
    int itile = blockIdx.x, r = blockIdx.y, split = blockIdx.z;
    int rowbase = itile * 128;
    int jw0 = split * 1024;

    __shared__ __align__(1024) uint8_t sB[2][8192];  // 64j x 64c f16, swizzled
    __shared__ uint32_t sBits[128 * 36];             // 128 rows, stride 36 words
    __shared__ uint4 sEF[256];                       // (group, tg) -> {E2lo,E2hi,F2lo,F2hi}
    __shared__ uint2 sLut[16];                       // nibble -> 2 half2 masks

    uint32_t sBu[2] = {(uint32_t)__cvta_generic_to_shared(&sB[0][0]),
                       (uint32_t)__cvta_generic_to_shared(&sB[1][0])};
    uint32_t sBitsu = (uint32_t)__cvta_generic_to_shared(sBits);
    uint32_t sEFu = (uint32_t)__cvta_generic_to_shared(sEF);

    if (tid < 16)
        sLut[tid] = make_uint2(
            ((tid & 1) ? 0xFFFFu : 0u) | ((tid & 2) ? 0xFFFF0000u : 0u),
            ((tid & 4) ? 0xFFFFu : 0u) | ((tid & 8) ? 0xFFFF0000u : 0u));

    // stage adjacency bits for this tile: 128 rows x 128B (once)
#pragma unroll
    for (int q = 0; q < 4; q++) {
        int idx = tid + 256 * q;
        int row = idx >> 3, w16 = idx & 7;
        const uint32_t* src = g_bits + (size_t)(r * NV + rowbase + row) * WPR +
                              split * 32 + w16 * 4;
        cpa16(sBitsu + (row * 36 + w16 * 4) * 4, src);
    }
    // stage EF window: 4KB (once)
    cpa16(sEFu + tid * 16,
          (const uint8_t*)g_EFj + (size_t)r * 16384 + split * 4096 + tid * 16);

    // B chunk stager: rows placed at sigma(j) to match lane-contiguous j perm
    auto stage = [&](int ch, int buf) {
#pragma unroll
        for (int q = 0; q < 2; q++) {
            int g = tid + 256 * q;
            int j64 = g >> 3, c8 = g & 7;
            int j16 = j64 & 15, t = j16 >> 2, q2 = j16 & 3;
            int srow = (j64 & ~15) + 2 * t + (q2 & 1) + ((q2 >> 1) << 3);
            const __half* src =
                g_Whh + ((size_t)(r * NV + jw0 + ch * 64 + j64)) * HD + c8 * 8;
            cpa16(sBu[buf] + srow * 128 + 16 * (c8 ^ (srow & 7)), src);
        }
        asm volatile("cp.async.commit_group;" ::: "memory");
    };
    stage(0, 0);

    int l = tid & 31, w = tid >> 5;
    int g4 = l >> 2, tg = l & 3;
    int rowg = rowbase + w * 16 + g4;
    uint32_t efi0 = g_EFi[r * NV + rowg];
    uint32_t efi1 = g_EFi[r * NV + rowg + 8];
    __half2 Ei2[2], Fi2[2];
    Ei2[0] = __low2half2(*(__half2*)&efi0);
    Fi2[0] = __high2half2(*(__half2*)&efi0);
    Ei2[1] = __low2half2(*(__half2*)&efi1);
    Fi2[1] = __high2half2(*(__half2*)&efi1);

    int row_l = ((l >> 3) & 1) * 8 + (l & 7);     // ldmatrix row within k16
    int x_l = (l >> 4) ^ (row_l & 7);             // swizzle term

    float acc[8][4] = {};
    float accD[4] = {};
    uint32_t bone = (l < 4) ? 0x3C003C00u : 0u;   // ones column (den)

    for (int ch = 0; ch < 16; ch++) {
        int buf = ch & 1;
        asm volatile("cp.async.wait_group 0;" ::: "memory");
        __syncthreads();
        if (ch + 1 < 16) stage(ch + 1, buf ^ 1);
        uint2 wb0 = *(const uint2*)&sBits[(w * 16 + g4) * 36 + ch * 2];
        uint2 wb1 = *(const uint2*)&sBits[(w * 16 + g4 + 8) * 36 + ch * 2];
#pragma unroll
        for (int ks = 0; ks < 4; ks++) {
            uint4 EF = sEF[ch * 16 + ks * 4 + tg];
            __half2 E2lo = *(__half2*)&EF.x, E2hi = *(__half2*)&EF.y;
            __half2 F2lo = *(__half2*)&EF.z, F2hi = *(__half2*)&EF.w;
            uint32_t afr[4];
#pragma unroll
            for (int rr = 0; rr < 2; rr++) {
                uint32_t wword = (ks < 2) ? (rr ? wb1.x : wb0.x)
                                          : (rr ? wb1.y : wb0.y);
                uint32_t nib = (wword >> ((ks & 1) * 16 + tg * 4)) & 0xFu;
                uint2 mk = sLut[nib];
                __half2 plo =
                    __hmax2(__hmul2(Ei2[rr], E2lo), __hmul2(Fi2[rr], F2lo));
                __half2 phi =
                    __hmax2(__hmul2(Ei2[rr], E2hi), __hmul2(Fi2[rr], F2hi));
                afr[rr] = (*reinterpret_cast<uint32_t*>(&plo)) & mk.x;
                afr[2 + rr] = (*reinterpret_cast<uint32_t*>(&phi)) & mk.y;
            }
            uint32_t rbase = sBu[buf] + (ks * 16 + row_l) * 128;
#pragma unroll
            for (int p = 0; p < 4; p++) {
                uint32_t b0, b1, b2, b3;
                asm volatile(
                    "ldmatrix.sync.aligned.m8n8.x4.trans.shared.b16 "
                    "{%0,%1,%2,%3}, [%4];"
                    : "=r"(b0), "=r"(b1), "=r"(b2), "=r"(b3)
                    : "r"(rbase + 16 * ((2 * p) ^ x_l)));
                mma16816(acc[2 * p], afr, b0, b1);
                mma16816(acc[2 * p + 1], afr, b2, b3);
            }
            mma16816(accD, afr, bone, bone);
        }
    }

    if (tg == 0) {
        g_den[(size_t)(r * 4 + split) * NV + rowg] = accD[0];
        g_den[(size_t)(r * 4 + split) * NV + rowg + 8] = accD[2];
    }
    float* nb = g_num + (size_t)(r * 4 + split) * NV * HD;
#pragma unroll
    for (int ng = 0; ng < 8; ng++) {
        int col = ng * 8 + tg * 2;
        *(float2*)&nb[(size_t)rowg * HD + col] =
            make_float2(acc[ng][0], acc[ng][1]);
        *(float2*)&nb[(size_t)(rowg + 8) * HD + col] =
            make_float2(acc[ng][2], acc[ng][3]);
    }
}

// ---------------- 5a. combine layer 1: bias + relu -> H1 ------------------------
__global__ void combine_kernel(const float* __restrict__ bvec) {
    int gid = blockIdx.x * 256 + threadIdx.x;
    int i = gid >> 6, c = gid & 63;
    float v = bvec[c];
#pragma unroll
    for (int r = 0; r < RV; r++) {
        float num = 0.f, den = 0.f;
#pragma unroll
        for (int s = 0; s < 4; s++) {
            num += g_num[(((size_t)(r * 4 + s) * NV) + i) * HD + c];
            den += g_den[(size_t)(r * 4 + s) * NV + i];
        }
        if (den != 0.f) v += num / den;
    }
    g_Hbuf[(size_t)i * HD + c] = fmaxf(v, 0.f);
}

// ---------------- 5b. combine layer 2 + score head fused ------------------------
__global__ void combine_score_kernel(const float* __restrict__ bvec,
                                     const float* __restrict__ Wsv,
                                     const float* __restrict__ bs,
                                     float* __restrict__ out) {
    __shared__ float s[8];
    int tid = threadIdx.x;
    int gid = blockIdx.x * 256 + tid;
    int i = gid >> 6, c = gid & 63;
    float v = bvec[c];
#pragma unroll
    for (int r = 0; r < RV; r++) {
        float num = 0.f, den = 0.f;
#pragma unroll
        for (int ss = 0; ss < 4; ss++) {
            num += g_num[(((size_t)(r * 4 + ss) * NV) + i) * HD + c];
            den += g_den[(size_t)(r * 4 + ss) * NV + i];
        }
        if (den != 0.f) v += num / den;
    }
    float p = fmaxf(v, 0.f) * Wsv[c];
#pragma unroll
    for (int o = 16; o; o >>= 1) p += __shfl_down_sync(0xFFFFFFFFu, p, o);
    int warp = tid >> 5, lane = tid & 31;
    if (lane == 0) s[warp] = p;
    __syncthreads();
    if (tid < 4) {
        float tot = s[2 * tid] + s[2 * tid + 1] + bs[0];
        out[blockIdx.x * 4 + tid] = 1.f / (1.f + __expf(-tot));
    }
}

// ---------------- launch --------------------------------------------------------
extern "C" void kernel_launch(void* const* d_in, const int* in_sizes, int n_in,
                              void* d_out, int out_size) {
    const float* Z  = (const float*)d_in[0];
    const int*   A0 = (const int*)d_in[1];
    const int*   A1 = (const int*)d_in[2];
    const int*   A2 = (const int*)d_in[3];
    const float* W1 = (const float*)d_in[4];
    const float* a1 = (const float*)d_in[5];
    const float* b1 = (const float*)d_in[6];
    const float* W2 = (const float*)d_in[7];
    const float* a2 = (const float*)d_in[8];
    const float* b2 = (const float*)d_in[9];
    const float* Ws = (const float*)d_in[10];
    const float* bs = (const float*)d_in[11];
    float* out = (float*)d_out;

    pack_kernel<<<4096, 256>>>(A0, A1, A2);

    // layer 1
    gemm_wh_kernel<128><<<dim3(64, 3), 256>>>(Z, 1, W1, a1);
    maxprep_kernel<<<dim3(16, 3), 256>>>();
    attn_hmma_kernel<<<dim3(32, 3, 4), 256>>>();
    combine_kernel<<<1024, 256>>>(b1);

    // layer 2
    gemm_wh_kernel<64><<<dim3(64, 3), 256>>>(nullptr, 0, W2, a2);
    maxprep_kernel<<<dim3(16, 3), 256>>>();
    attn_hmma_kernel<<<dim3(32, 3, 4), 256>>>();
    combine_score_kernel<<<1024, 256>>>(b2, Ws, bs, out);
}

// round 6
// speedup vs baseline: 5.3468x; 1.0139x over previous
#include <cuda_runtime.h>
#include <cuda_fp16.h>
#include <cstdint>
#include <math.h>

#define NV 4096
#define HD 64
#define RV 3
#define WPR 128   // 32-bit words per adjacency row

// ---------------- scratch ------------------------------------------------------
__device__ uint32_t g_bits[RV * NV * WPR];        // packed adjacency (6.3 MB)
__device__ float g_fi[RV * NV];
__device__ float g_fj[RV * NV];
__device__ uint32_t g_EFi[RV * NV];               // half2(Ei, Fi) per row
__device__ uint4 g_EFj[RV * 256 * 4];             // per 16-j group x tg: {E2lo,E2hi,F2lo,F2hi}
__device__ __half g_Whh[RV * NV * HD];            // Wh in f16, [r][j][c]
__device__ float g_Hbuf[NV * HD];                 // H1
__device__ float g_num[RV * 4 * NV * HD];         // per (r, j-split) numerators
__device__ float g_den[RV * 4 * NV];

__device__ __forceinline__ float lrelu(float x) { return x > 0.f ? x : 0.2f * x; }

__device__ __forceinline__ void cpa16(uint32_t d, const void* s) {
    asm volatile("cp.async.cg.shared.global [%0], [%1], 16;" :: "r"(d), "l"(s));
}
__device__ __forceinline__ void mma16816(float* d, const uint32_t* a,
                                         uint32_t b0, uint32_t b1) {
    asm volatile(
        "mma.sync.aligned.m16n8k16.row.col.f32.f16.f16.f32 "
        "{%0,%1,%2,%3}, {%4,%5,%6,%7}, {%8,%9}, {%0,%1,%2,%3};"
        : "+f"(d[0]), "+f"(d[1]), "+f"(d[2]), "+f"(d[3])
        : "r"(a[0]), "r"(a[1]), "r"(a[2]), "r"(a[3]), "r"(b0), "r"(b1));
}

// ---------------- 1. pack adjacency to bits (grid-stride, vectorized) ----------
__global__ void pack_kernel(const int* __restrict__ A0, const int* __restrict__ A1,
                            const int* __restrict__ A2) {
    const int TOTQ = RV * NV * NV / 4;            // int4 quads
    int stride = gridDim.x * blockDim.x;
    int lane = threadIdx.x & 31;
    for (int t = blockIdx.x * blockDim.x + threadIdx.x; t < TOTQ; t += stride) {
        int r = t >> 22;                          // (4t) >> 24
        const int4* A = (const int4*)((r == 0) ? A0 : (r == 1) ? A1 : A2);
        int4 v = A[t & 0x3FFFFF];
        uint32_t nib = (v.x != 0 ? 1u : 0u) | (v.y != 0 ? 2u : 0u) |
                       (v.z != 0 ? 4u : 0u) | (v.w != 0 ? 8u : 0u);
        uint32_t m = nib << ((lane & 7) * 4);
        m |= __shfl_xor_sync(0xFFFFFFFFu, m, 1);
        m |= __shfl_xor_sync(0xFFFFFFFFu, m, 2);
        m |= __shfl_xor_sync(0xFFFFFFFFu, m, 4);
        if ((lane & 7) == 0) g_bits[t >> 3] = m;
    }
}

// ---------------- 2. Wh = H @ W[r]; emits Whh(f16,[j][c]) + f_i/f_j -------------
template <int K>
__global__ void gemm_wh_kernel(const float* __restrict__ Hext, int useExt,
                               const float* __restrict__ Wmat,
                               const float* __restrict__ avec) {
    const float* H = useExt ? Hext : g_Hbuf;
    int r = blockIdx.y;
    int rowbase = blockIdx.x * 64;
    __shared__ float Hs[64][64];                  // [k][i] then reused [i][c]
    __shared__ float Wss[64][64];                 // [k][c]
    int tid = threadIdx.x;
    int tx = tid & 15, ty = tid >> 4;
    int i0 = ty * 4, c0 = tx * 4;
    float acc[4][4] = {};
    const float* Wr = Wmat + (size_t)r * K * HD;

    for (int kt = 0; kt < K; kt += 64) {
        {
            int i = tid >> 2, kk0 = (tid & 3) << 4;
            const float* src = H + (size_t)(rowbase + i) * K + kt + kk0;
#pragma unroll
            for (int q = 0; q < 4; q++) {
                float4 v = *(const float4*)(src + 4 * q);
                Hs[kk0 + 4 * q + 0][i] = v.x;
                Hs[kk0 + 4 * q + 1][i] = v.y;
                Hs[kk0 + 4 * q + 2][i] = v.z;
                Hs[kk0 + 4 * q + 3][i] = v.w;
            }
            const float4* wsrc = (const float4*)(Wr + (size_t)kt * HD);
            float4* wdst = (float4*)&Wss[0][0];
#pragma unroll
            for (int q = 0; q < 4; q++) wdst[tid + 256 * q] = wsrc[tid + 256 * q];
        }
        __syncthreads();
#pragma unroll 8
        for (int kk = 0; kk < 64; kk++) {
            float4 a = *(const float4*)&Hs[kk][i0];
            float4 b = *(const float4*)&Wss[kk][c0];
            float av[4] = {a.x, a.y, a.z, a.w};
            float bv[4] = {b.x, b.y, b.z, b.w};
#pragma unroll
            for (int ii = 0; ii < 4; ii++)
#pragma unroll
                for (int jj = 0; jj < 4; jj++)
                    acc[ii][jj] = fmaf(av[ii], bv[jj], acc[ii][jj]);
        }
        __syncthreads();
    }

#pragma unroll
    for (int ii = 0; ii < 4; ii++)
        *(float4*)&Hs[i0 + ii][c0] =
            make_float4(acc[ii][0], acc[ii][1], acc[ii][2], acc[ii][3]);
    __syncthreads();

    // f16 Wh store: [j][c]
    {
        int i = tid >> 2, cb = (tid & 3) * 16;
        uint32_t h2v[8];
#pragma unroll
        for (int q = 0; q < 8; q++) {
            __half2 h = __floats2half2_rn(Hs[i][cb + 2 * q], Hs[i][cb + 2 * q + 1]);
            h2v[q] = *reinterpret_cast<uint32_t*>(&h);
        }
        uint32_t* dst =
            (uint32_t*)(g_Whh + ((size_t)(r * NV + rowbase + i)) * HD + cb);
        *(uint4*)dst = make_uint4(h2v[0], h2v[1], h2v[2], h2v[3]);
        *(uint4*)(dst + 4) = make_uint4(h2v[4], h2v[5], h2v[6], h2v[7]);
    }

    int warp = tid >> 5, lane = tid & 31;
    const float* ar = avec + r * 2 * HD;
#pragma unroll
    for (int s = 0; s < 8; s++) {
        int i = warp * 8 + s;
        float h1 = Hs[i][lane], h2 = Hs[i][lane + 32];
        float pl = h1 * ar[lane] + h2 * ar[lane + 32];
        float pr = h1 * ar[HD + lane] + h2 * ar[HD + lane + 32];
#pragma unroll
        for (int o = 16; o; o >>= 1) {
            pl += __shfl_down_sync(0xFFFFFFFFu, pl, o);
            pr += __shfl_down_sync(0xFFFFFFFFu, pr, o);
        }
        if (lane == 0) {
            g_fi[r * NV + rowbase + i] = pl;
            g_fj[r * NV + rowbase + i] = pr;
        }
    }
}

// ---------------- 3. fused max(f_j) + softmax factors (f16 packed) --------------
__global__ void maxprep_kernel() {
    int r = blockIdx.y, tid = threadIdx.x;
    __shared__ float s[256];
    float m = -INFINITY;
    for (int j = tid; j < NV; j += 256) m = fmaxf(m, g_fj[r * NV + j]);
    s[tid] = m;
    __syncthreads();
    for (int o = 128; o; o >>= 1) {
        if (tid < o) s[tid] = fmaxf(s[tid], s[tid + o]);
        __syncthreads();
    }
    float Mj = s[0];
    int i = blockIdx.x * 256 + tid;
    float fi = g_fi[r * NV + i], fj = g_fj[r * NV + i];
    float u = fi + Mj;
    float mm = lrelu(u);
    __half2 efi = __floats2half2_rn(__expf(u - mm), __expf(0.2f * u - mm));
    g_EFi[r * NV + i] = *reinterpret_cast<uint32_t*>(&efi);
    // scatter Ej/Fj into the lane-permuted uint4 layout
    int g = i >> 4, j16 = i & 15, t = j16 >> 2, q = j16 & 3;
    __half* dst = (__half*)g_EFj + (size_t)r * NV * 2 + (g * 4 + t) * 8 + q;
    dst[0] = __float2half_rn(__expf(fj - Mj));
    dst[4] = __float2half_rn(__expf(0.2f * (fj - Mj)));
}

// ---------------- 4. fused alpha-gen + HMMA aggregation -------------------------
// grid (32 i-tiles of 128 rows, 3 r, 4 j-splits of 1024); 128 threads / 4 warps.
// Each warp owns 32 rows (2 m16 tiles) x all 64 cols: B fragments reused 2x.
__global__ void __launch_bounds__(128, 4) attn_hmma_kernel() {
    int tid = threadIdx.x;
    int itile = blockIdx.x, r = blockIdx.y, split = blockIdx.z;
    int rowbase = itile * 128;
    int jw0 = split * 1024;

    __shared__ __align__(1024) uint8_t sB[2][8192];  // 64j x 64c f16, swizzled
    __shared__ uint32_t sBits[128 * 36];             // 128 rows, stride 36 words
    __shared__ uint4 sEF[256];                       // (group, tg) -> {E2lo,E2hi,F2lo,F2hi}
    __shared__ uint2 sLut[16];                       // nibble -> 2 half2 masks

    uint32_t sBu[2] = {(uint32_t)__cvta_generic_to_shared(&sB[0][0]),
                       (uint32_t)__cvta_generic_to_shared(&sB[1][0])};
    uint32_t sBitsu = (uint32_t)__cvta_generic_to_shared(sBits);
    uint32_t sEFu = (uint32_t)__cvta_generic_to_shared(sEF);

    if (tid < 16)
        sLut[tid] = make_uint2(
            ((tid & 1) ? 0xFFFFu : 0u) | ((tid & 2) ? 0xFFFF0000u : 0u),
            ((tid & 4) ? 0xFFFFu : 0u) | ((tid & 8) ? 0xFFFF0000u : 0u));

    // stage adjacency bits for this tile: 128 rows x 128B (once)
#pragma unroll
    for (int q = 0; q < 8; q++) {
        int idx = tid + 128 * q;
        int row = idx >> 3, w16 = idx & 7;
        const uint32_t* src = g_bits + (size_t)(r * NV + rowbase + row) * WPR +
                              split * 32 + w16 * 4;
        cpa16(sBitsu + (row * 36 + w16 * 4) * 4, src);
    }
    // stage EF window: 4KB (once)
#pragma unroll
    for (int q = 0; q < 2; q++)
        cpa16(sEFu + (tid + 128 * q) * 16,
              (const uint8_t*)g_EFj + (size_t)r * 16384 + split * 4096 +
                  (tid + 128 * q) * 16);

    // B chunk stager: rows placed at sigma(j) to match lane-contiguous j perm
    auto stage = [&](int ch, int buf) {
#pragma unroll
        for (int q = 0; q < 4; q++) {
            int g = tid + 128 * q;
            int j64 = g >> 3, c8 = g & 7;
            int j16 = j64 & 15, t = j16 >> 2, q2 = j16 & 3;
            int srow = (j64 & ~15) + 2 * t + (q2 & 1) + ((q2 >> 1) << 3);
            const __half* src =
                g_Whh + ((size_t)(r * NV + jw0 + ch * 64 + j64)) * HD + c8 * 8;
            cpa16(sBu[buf] + srow * 128 + 16 * (c8 ^ (srow & 7)), src);
        }
        asm volatile("cp.async.commit_group;" ::: "memory");
    };
    stage(0, 0);

    int l = tid & 31, w = tid >> 5;
    int g4 = l >> 2, tg = l & 3;
    int rowloc = w * 32 + g4;                     // rows rowloc + 8*rr, rr<4
    int rowg = rowbase + rowloc;
    __half2 Ei2[4], Fi2[4];
#pragma unroll
    for (int rr = 0; rr < 4; rr++) {
        uint32_t efi = g_EFi[r * NV + rowg + 8 * rr];
        Ei2[rr] = __low2half2(*(__half2*)&efi);
        Fi2[rr] = __high2half2(*(__half2*)&efi);
    }

    int row_l = ((l >> 3) & 1) * 8 + (l & 7);     // ldmatrix row within k16
    int x_l = (l >> 4) ^ (row_l & 7);             // swizzle term

    float acc[2][8][4] = {};                      // [m-tile][n8][frag]
    float accD[2][4] = {};
    uint32_t bone = (l < 4) ? 0x3C003C00u : 0u;   // ones column (den)

    for (int ch = 0; ch < 16; ch++) {
        int buf = ch & 1;
        asm volatile("cp.async.wait_group 0;" ::: "memory");
        __syncthreads();
        if (ch + 1 < 16) stage(ch + 1, buf ^ 1);
        uint2 wbv[4];
#pragma unroll
        for (int rr = 0; rr < 4; rr++)
            wbv[rr] = *(const uint2*)&sBits[(rowloc + 8 * rr) * 36 + ch * 2];
#pragma unroll
        for (int ks = 0; ks < 4; ks++) {
            uint4 EF = sEF[ch * 16 + ks * 4 + tg];
            __half2 E2lo = *(__half2*)&EF.x, E2hi = *(__half2*)&EF.y;
            __half2 F2lo = *(__half2*)&EF.z, F2hi = *(__half2*)&EF.w;
            uint32_t afr[2][4];
#pragma unroll
            for (int rr = 0; rr < 4; rr++) {
                uint32_t wword = (ks < 2) ? wbv[rr].x : wbv[rr].y;
                uint32_t nib = (wword >> ((ks & 1) * 16 + tg * 4)) & 0xFu;
                uint2 mk = sLut[nib];
                __half2 plo =
                    __hmax2(__hmul2(Ei2[rr], E2lo), __hmul2(Fi2[rr], F2lo));
                __half2 phi =
                    __hmax2(__hmul2(Ei2[rr], E2hi), __hmul2(Fi2[rr], F2hi));
                int mt = rr >> 1, hi = rr & 1;
                afr[mt][hi] = (*reinterpret_cast<uint32_t*>(&plo)) & mk.x;
                afr[mt][2 + hi] = (*reinterpret_cast<uint32_t*>(&phi)) & mk.y;
            }
            uint32_t rbase = sBu[buf] + (ks * 16 + row_l) * 128;
#pragma unroll
            for (int p = 0; p < 4; p++) {
                uint32_t b0, b1, b2, b3;
                asm volatile(
                    "ldmatrix.sync.aligned.m8n8.x4.trans.shared.b16 "
                    "{%0,%1,%2,%3}, [%4];"
                    : "=r"(b0), "=r"(b1), "=r"(b2), "=r"(b3)
                    : "r"(rbase + 16 * ((2 * p) ^ x_l)));
                mma16816(acc[0][2 * p], afr[0], b0, b1);
                mma16816(acc[0][2 * p + 1], afr[0], b2, b3);
                mma16816(acc[1][2 * p], afr[1], b0, b1);
                mma16816(acc[1][2 * p + 1], afr[1], b2, b3);
            }
            mma16816(accD[0], afr[0], bone, bone);
            mma16816(accD[1], afr[1], bone, bone);
        }
    }

    if (tg == 0) {
#pragma unroll
        for (int mt = 0; mt < 2; mt++) {
            g_den[(size_t)(r * 4 + split) * NV + rowg + 16 * mt] = accD[mt][0];
            g_den[(size_t)(r * 4 + split) * NV + rowg + 16 * mt + 8] = accD[mt][2];
        }
    }
    float* nb = g_num + (size_t)(r * 4 + split) * NV * HD;
#pragma unroll
    for (int mt = 0; mt < 2; mt++)
#pragma unroll
        for (int ng = 0; ng < 8; ng++) {
            int col = ng * 8 + tg * 2;
            int R0 = rowg + 16 * mt;
            *(float2*)&nb[(size_t)R0 * HD + col] =
                make_float2(acc[mt][ng][0], acc[mt][ng][1]);
            *(float2*)&nb[(size_t)(R0 + 8) * HD + col] =
                make_float2(acc[mt][ng][2], acc[mt][ng][3]);
        }
}

// ---------------- 5a. combine layer 1: bias + relu -> H1 (float4) ---------------
__global__ void combine_kernel(const float* __restrict__ bvec) {
    int gid = blockIdx.x * 256 + threadIdx.x;     // NV*HD/4 = 65536 threads
    int i = gid >> 4, c4 = (gid & 15) * 4;
    float4 v = *(const float4*)&bvec[c4];
#pragma unroll
    for (int r = 0; r < RV; r++) {
        float4 num = make_float4(0.f, 0.f, 0.f, 0.f);
        float den = 0.f;
#pragma unroll
        for (int s = 0; s < 4; s++) {
            float4 nv = *(const float4*)&g_num[(((size_t)(r * 4 + s) * NV) + i) * HD + c4];
            num.x += nv.x; num.y += nv.y; num.z += nv.z; num.w += nv.w;
            den += g_den[(size_t)(r * 4 + s) * NV + i];
        }
        if (den != 0.f) {
            float inv = __frcp_rn(den);
            v.x += num.x * inv; v.y += num.y * inv;
            v.z += num.z * inv; v.w += num.w * inv;
        }
    }
    v.x = fmaxf(v.x, 0.f); v.y = fmaxf(v.y, 0.f);
    v.z = fmaxf(v.z, 0.f); v.w = fmaxf(v.w, 0.f);
    *(float4*)&g_Hbuf[(size_t)i * HD + c4] = v;
}

// ---------------- 5b. combine layer 2 + score head fused (float4) ---------------
__global__ void combine_score_kernel(const float* __restrict__ bvec,
                                     const float* __restrict__ Wsv,
                                     const float* __restrict__ bs,
                                     float* __restrict__ out) {
    int tid = threadIdx.x;
    int gid = blockIdx.x * 256 + tid;
    int i = gid >> 4, c4 = (gid & 15) * 4;
    float4 v = *(const float4*)&bvec[c4];
#pragma unroll
    for (int r = 0; r < RV; r++) {
        float4 num = make_float4(0.f, 0.f, 0.f, 0.f);
        float den = 0.f;
#pragma unroll
        for (int s = 0; s < 4; s++) {
            float4 nv = *(const float4*)&g_num[(((size_t)(r * 4 + s) * NV) + i) * HD + c4];
            num.x += nv.x; num.y += nv.y; num.z += nv.z; num.w += nv.w;
            den += g_den[(size_t)(r * 4 + s) * NV + i];
        }
        if (den != 0.f) {
            float inv = __frcp_rn(den);
            v.x += num.x * inv; v.y += num.y * inv;
            v.z += num.z * inv; v.w += num.w * inv;
        }
    }
    float4 ws = *(const float4*)&Wsv[c4];
    float p = fmaxf(v.x, 0.f) * ws.x + fmaxf(v.y, 0.f) * ws.y +
              fmaxf(v.z, 0.f) * ws.z + fmaxf(v.w, 0.f) * ws.w;
#pragma unroll
    for (int o = 8; o; o >>= 1) p += __shfl_down_sync(0xFFFFFFFFu, p, o, 16);
    if ((tid & 15) == 0) out[i] = 1.f / (1.f + __expf(-(p + bs[0])));
}

// ---------------- launch --------------------------------------------------------
extern "C" void kernel_launch(void* const* d_in, const int* in_sizes, int n_in,
                              void* d_out, int out_size) {
    const float* Z  = (const float*)d_in[0];
    const int*   A0 = (const int*)d_in[1];
    const int*   A1 = (const int*)d_in[2];
    const int*   A2 = (const int*)d_in[3];
    const float* W1 = (const float*)d_in[4];
    const float* a1 = (const float*)d_in[5];
    const float* b1 = (const float*)d_in[6];
    const float* W2 = (const float*)d_in[7];
    const float* a2 = (const float*)d_in[8];
    const float* b2 = (const float*)d_in[9];
    const float* Ws = (const float*)d_in[10];
    const float* bs = (const float*)d_in[11];
    float* out = (float*)d_out;

    pack_kernel<<<4096, 256>>>(A0, A1, A2);

    // layer 1
    gemm_wh_kernel<128><<<dim3(64, 3), 256>>>(Z, 1, W1, a1);
    maxprep_kernel<<<dim3(16, 3), 256>>>();
    attn_hmma_kernel<<<dim3(32, 3, 4), 128>>>();
    combine_kernel<<<256, 256>>>(b1);

    // layer 2
    gemm_wh_kernel<64><<<dim3(64, 3), 256>>>(nullptr, 0, W2, a2);
    maxprep_kernel<<<dim3(16, 3), 256>>>();
    attn_hmma_kernel<<<dim3(32, 3, 4), 128>>>();
    combine_score_kernel<<<256, 256>>>(b2, Ws, bs, out);
}